// round 15
// baseline (speedup 1.0000x reference)
#include <cuda_runtime.h>
#include <math.h>

#define BB    8
#define CC    256
#define NCLS  20
#define APER  2
#define LTOT  3584
#define ATOT  7168
#define KTOP  1000
#define NSORT 8192

typedef unsigned long long u64;

// ---------------- scratch (device globals; no allocation) ----------------
__device__ float g_bufA[BB * CC * LTOT];   // cls ping
__device__ float g_bufB[BB * CC * LTOT];   // cls pong
__device__ float g_bufC[BB * CC * LTOT];   // reg ping
__device__ float g_bufD[BB * CC * LTOT];   // reg pong
__device__ float g_Gc[3 * BB * CC * LTOT]; // per-kw partials, cls tower
__device__ float g_Gr[3 * BB * CC * LTOT]; // per-kw partials, reg tower
__device__ u64   g_wt2[2 * 4 * 3 * CC * CC]; // dup-packed weights [tower][layer][kw][ci][co]
__device__ float g_logits[BB * APER * NCLS * LTOT];
__device__ float g_regs[BB * APER * 2 * LTOT];
__device__ float g_segs[BB * ATOT * 2];
__device__ unsigned long long g_keys[BB * NSORT];
__device__ unsigned long long g_topkeys[BB * KTOP];

__device__ __forceinline__ u64 fma2(u64 a, u64 b, u64 c)
{
    u64 d;
    asm("fma.rn.f32x2 %0, %1, %2, %3;" : "=l"(d) : "l"(a), "l"(b), "l"(c));
    return d;
}

// ---------------- weight transpose+duplicate (ALL layers) ----------------
__global__ void wtrans_kernel(const float* __restrict__ wc,
                              const float* __restrict__ wr)
{
    int idx = blockIdx.x * 256 + threadIdx.x;      // 0 .. 2*786432-1
    int tower = idx / 786432;
    int r = idx - tower * 786432;                  // [layer][kw][ci][co]
    int layer = r / 196608;
    int rr = r - layer * 196608;
    int kw = rr / 65536;
    int rem = rr - kw * 65536;
    int ci = rem >> 8;
    int co = rem & 255;
    const float* w = tower ? wr : wc;
    float v = w[layer * 196608 + co * 768 + ci * 3 + kw];
    unsigned bits = __float_as_uint(v);
    g_wt2[idx] = ((u64)bits << 32) | (u64)bits;
}

// ---------------- per-kw GEMM: R14 config + dup-w (no pk MOVs) -----------
// G_kw[co][l] = sum_ci wt[kw][ci][co] * x[ci][l]; single sequential fma
// chain per output lane over ci=0..255 (one Eigen k-block); bit-exact.
__global__ void __launch_bounds__(256, 2) gemm_kernel(
    const float* __restrict__ f3, const float* __restrict__ f4,
    const float* __restrict__ f5,
    const float* __restrict__ xc, const float* __restrict__ xr,
    int layer)
{
    __shared__ float xs[2][16][128];
    __shared__ u64   ws[2][16][128];

    const int tid = threadIdx.x;
    const int lbb = blockIdx.x;
    const int b = lbb / 28;
    const int lb = lbb - b * 28;
    const int lvl = (lb < 16) ? 0 : ((lb < 24) ? 1 : 2);
    const int Ls[3]  = {2048, 1024, 512};
    const int off[3] = {0, 2048, 3072};
    const int st[3]  = {0, 16, 24};
    const int lBase = (lb - st[lvl]) * 128;
    const int coBase = blockIdx.y * 128;
    const int z = blockIdx.z;
    const int tower = z / 3;
    const int kw = z - tower * 3;

    const float* x;
    int xcs_;
    long long xofs;
    if (layer == 0) {
        x = (lvl == 0) ? f3 : ((lvl == 1) ? f4 : f5);
        xcs_ = Ls[lvl];
        xofs = (long long)b * (256 * Ls[lvl]);
    } else {
        x = tower ? xr : xc;
        xcs_ = LTOT;
        xofs = (long long)b * (256 * LTOT) + off[lvl];
    }
    const u64* wt2 = g_wt2 + (((long long)(tower * 4 + layer) * 3 + kw) << 16) + coBase;
    float* G = tower ? g_Gr : g_Gc;

    u64 acc2[8][4];
#pragma unroll
    for (int o = 0; o < 8; o++)
#pragma unroll
        for (int p = 0; p < 4; p++) acc2[o][p] = 0ULL;

    const int lg = tid & 15;
    const int cg = tid >> 4;
    const int lb8 = lg * 8;
    const int cb = cg * 8;

    const int ldrow = tid >> 4;        // 0..15 (ci within chunk)
    const int ldcol = (tid & 15) * 8;  // x float col / w u64 col

    const float* xbase = x + xofs + (long long)ldrow * xcs_ + lBase + ldcol;
    const u64* wbase = wt2 + ldrow * 256 + ldcol;

#define ISSUE(c0, stg) do {                                                   \
        const float* xp = xbase + (long long)(c0) * xcs_;                     \
        unsigned xd = (unsigned)__cvta_generic_to_shared(&xs[stg][ldrow][ldcol]); \
        asm volatile("cp.async.ca.shared.global [%0], [%1], 16;" ::  "r"(xd), "l"(xp) : "memory"); \
        asm volatile("cp.async.ca.shared.global [%0], [%1], 16;" ::  "r"(xd + 16), "l"(xp + 4) : "memory"); \
        const u64* wp = wbase + (c0) * 256;                                   \
        unsigned wd = (unsigned)__cvta_generic_to_shared(&ws[stg][ldrow][ldcol]); \
        asm volatile("cp.async.ca.shared.global [%0], [%1], 16;" ::  "r"(wd), "l"(wp) : "memory"); \
        asm volatile("cp.async.ca.shared.global [%0], [%1], 16;" ::  "r"(wd + 16), "l"(wp + 2) : "memory"); \
        asm volatile("cp.async.ca.shared.global [%0], [%1], 16;" ::  "r"(wd + 32), "l"(wp + 4) : "memory"); \
        asm volatile("cp.async.ca.shared.global [%0], [%1], 16;" ::  "r"(wd + 48), "l"(wp + 6) : "memory"); \
        asm volatile("cp.async.commit_group;" ::: "memory");                  \
    } while (0)

    ISSUE(0, 0);

    for (int n = 0; n < 16; n++) {
        const int stg = n & 1;
        if (n < 15) {
            ISSUE(n * 16 + 16, stg ^ 1);
            asm volatile("cp.async.wait_group 1;" ::: "memory");
        } else {
            asm volatile("cp.async.wait_group 0;" ::: "memory");
        }
        __syncthreads();

#pragma unroll
        for (int ci = 0; ci < 16; ci++) {
            ulonglong2 xa = *(const ulonglong2*)&xs[stg][ci][lb8];
            ulonglong2 xb = *(const ulonglong2*)&xs[stg][ci][lb8 + 4];
            const ulonglong2* wrow = (const ulonglong2*)&ws[stg][ci][cb];
            ulonglong2 w0 = wrow[0];
            ulonglong2 w1 = wrow[1];
            ulonglong2 w2 = wrow[2];
            ulonglong2 w3 = wrow[3];
            u64 xv[4] = {xa.x, xa.y, xb.x, xb.y};
            u64 wv[8] = {w0.x, w0.y, w1.x, w1.y, w2.x, w2.y, w3.x, w3.y};
#pragma unroll
            for (int o = 0; o < 8; o++)
#pragma unroll
                for (int p = 0; p < 4; p++)
                    acc2[o][p] = fma2(wv[o], xv[p], acc2[o][p]);
        }
        __syncthreads();
    }
#undef ISSUE

#pragma unroll
    for (int o = 0; o < 8; o++) {
        u64* gp = (u64*)(G + ((long long)((kw * BB + b) * CC + coBase + cb + o)) * LTOT
                           + off[lvl] + lBase + lb8);
#pragma unroll
        for (int p = 0; p < 4; p++) gp[p] = acc2[o][p];
    }
}

// ---------------- combine: one block per row, high MLP -------------------
// out[l] = relu(((G0[l-1] + G1[l]) + G2[l+1]) + bias), zeros at level edges.
// Block: 896 threads x 4 floats = whole 3584-l row of one (tower,b,co).
__global__ void __launch_bounds__(896) combine_kernel(
    float* __restrict__ outc, float* __restrict__ outr,
    const float* __restrict__ bc, const float* __restrict__ br)
{
    __shared__ float s0[3585];   // s0[l] = G0[l-1] (0 at level starts)
    __shared__ float s2[3585];   // s2[l] = G2[l]   (0 at level starts, s2[3584]=0)

    const int tid = threadIdx.x;
    const int row = blockIdx.x;            // tower*2048 + b*256 + co
    const int co = row & 255;
    const int b = (row >> 8) & 7;
    const int tower = row >> 11;

    const float* G = tower ? g_Gr : g_Gc;
    long long base = ((long long)b * CC + co) * LTOT;
    const float* G0 = G + base;
    const float* G1 = G + (long long)BB * CC * LTOT + base;
    const float* G2 = G + 2LL * BB * CC * LTOT + base;
    float bias = (tower ? br : bc)[co];
    float* out = (tower ? outr : outc) + base;

    const int l4 = tid * 4;
    float4 a0 = *(const float4*)(G0 + l4);
    float4 a2 = *(const float4*)(G2 + l4);
    // s0[1+l] = G0[l], but zero where 1+l is a level start (2048, 3072)
    s0[1 + l4]     = (l4     == 2047 || l4     == 3071) ? 0.f : a0.x;
    s0[1 + l4 + 1] = (l4 + 1 == 2047 || l4 + 1 == 3071) ? 0.f : a0.y;
    s0[1 + l4 + 2] = (l4 + 2 == 2047 || l4 + 2 == 3071) ? 0.f : a0.z;
    s0[1 + l4 + 3] = (l4 + 3 == 2047 || l4 + 3 == 3071) ? 0.f : a0.w;
    // s2[l] = G2[l], but zero at level starts (2048, 3072)
    s2[l4]     = (l4     == 2048 || l4     == 3072) ? 0.f : a2.x;
    s2[l4 + 1] = a2.y;
    s2[l4 + 2] = a2.z;
    s2[l4 + 3] = a2.w;
    if (tid == 0) { s0[0] = 0.f; s2[3584] = 0.f; }
    __syncthreads();

    float4 g1 = *(const float4*)(G1 + l4);
    float4 r;
    r.x = fmaxf(__fadd_rn(__fadd_rn(__fadd_rn(s0[l4],     g1.x), s2[l4 + 1]), bias), 0.f);
    r.y = fmaxf(__fadd_rn(__fadd_rn(__fadd_rn(s0[l4 + 1], g1.y), s2[l4 + 2]), bias), 0.f);
    r.z = fmaxf(__fadd_rn(__fadd_rn(__fadd_rn(s0[l4 + 2], g1.z), s2[l4 + 3]), bias), 0.f);
    r.w = fmaxf(__fadd_rn(__fadd_rn(__fadd_rn(s0[l4 + 3], g1.w), s2[l4 + 4]), bias), 0.f);
    *(float4*)(out + l4) = r;
}

// ---------------- fused prediction conv: x staged ONCE, 3 kw accums ------
__global__ void __launch_bounds__(320) convpred_kernel(
    const float* __restrict__ xc, const float* __restrict__ xr,
    const float* __restrict__ wcp, const float* __restrict__ wrp,
    const float* __restrict__ bcp, const float* __restrict__ brp,
    float* __restrict__ logits, float* __restrict__ regs)
{
    __shared__ float xs[32][72];
    __shared__ float ws[32][3][40];

    const int Ls[3]  = {2048, 1024, 512};
    const int off[3] = {0, 2048, 3072};
    const int st[3]  = {0, 32, 48};

    const int tid = threadIdx.x;
    const int pb = blockIdx.x;
    const int lvl = (pb < 32) ? 0 : ((pb < 48) ? 1 : 2);
    const int lBase = (pb - st[lvl]) * 64;
    const int b = blockIdx.y;
    const int tower = blockIdx.z;
    const int L = Ls[lvl];

    const int Cout = tower ? (APER * 2) : (APER * NCLS);
    const float* w = tower ? wrp : wcp;
    const float* bias = tower ? brp : bcp;
    const float* xb = (tower ? xr : xc) + (long long)b * (CC * LTOT) + off[lvl];
    float* y = (tower ? regs : logits) + (long long)b * (Cout * LTOT) + off[lvl];

    const int co = tid >> 3;
    const int lg = tid & 7;

    float p0[8], p1[8], p2[8];
#pragma unroll
    for (int q = 0; q < 8; q++) { p0[q] = 0.f; p1[q] = 0.f; p2[q] = 0.f; }

    const int wcount = Cout * 96;
    for (int c0 = 0; c0 < 256; c0 += 32) {
        for (int idx = tid; idx < 32 * 66; idx += 320) {
            int ci = idx / 66;
            int ll = idx - ci * 66;
            int gl = lBase + ll - 1;
            xs[ci][ll] = (gl >= 0 && gl < L) ? xb[(long long)(c0 + ci) * LTOT + gl] : 0.f;
        }
        for (int idx = tid; idx < wcount; idx += 320) {
            int c = idx / 96;
            int rem = idx - c * 96;
            int r = rem / 3;
            int kw = rem - r * 3;
            ws[r][kw][c] = w[c * 768 + (c0 + r) * 3 + kw];
        }
        __syncthreads();

        if (co < Cout) {
#pragma unroll
            for (int ci = 0; ci < 32; ci++) {
                float xv[10];
#pragma unroll
                for (int j = 0; j < 10; j++) xv[j] = xs[ci][lg * 8 + j];
                float w0 = ws[ci][0][co];
                float w1 = ws[ci][1][co];
                float w2 = ws[ci][2][co];
#pragma unroll
                for (int q = 0; q < 8; q++) {
                    p0[q] = fmaf(w0, xv[q],     p0[q]);
                    p1[q] = fmaf(w1, xv[q + 1], p1[q]);
                    p2[q] = fmaf(w2, xv[q + 2], p2[q]);
                }
            }
        }
        __syncthreads();
    }

    if (co < Cout) {
        float bv = bias[co];
#pragma unroll
        for (int q = 0; q < 8; q++)
            y[(long long)co * LTOT + lBase + lg * 8 + q] =
                __fadd_rn(__fadd_rn(__fadd_rn(p0[q], p1[q]), p2[q]), bv);
    }
}

// ---------------- per-anchor sort key (logit bits) + decoded segment ----
__global__ void score_kernel()
{
    int id = blockIdx.x * 256 + threadIdx.x;
    int b = id >> 13;
    int a = id & (NSORT - 1);
    if (a >= ATOT) { g_keys[id] = 0ULL; return; }

    int lvl, al;
    if (a < 4096)      { lvl = 0; al = a; }
    else if (a < 6144) { lvl = 1; al = a - 4096; }
    else               { lvl = 2; al = a - 6144; }

    const int   Ls[3]     = {2048, 1024, 512};
    const int   off[3]    = {0, 2048, 3072};
    const int   strides[3]= {8, 16, 32};
    const float lens[3][2]= {{16.f, 32.f}, {64.f, 128.f}, {256.f, 512.f}};

    int L = Ls[lvl];
    int ap = al / L;
    int l  = al - ap * L;

    const float* lp = g_logits + ((long long)(b * APER + ap) * NCLS) * LTOT + off[lvl] + l;
    float m = -1e30f;
#pragma unroll
    for (int c = 0; c < NCLS; c++) m = fmaxf(m, lp[c * LTOT]);

    unsigned mb = __float_as_uint(m);
    mb ^= (mb & 0x80000000u) ? 0xFFFFFFFFu : 0x80000000u;
    unsigned long long key =
        ((unsigned long long)mb << 32) |
        (unsigned long long)(0xFFFFFFFFu - (unsigned)a);
    g_keys[id] = key;

    float r0 = g_regs[((long long)(b * APER + ap) * 2 + 0) * LTOT + off[lvl] + l];
    float r1 = g_regs[((long long)(b * APER + ap) * 2 + 1) * LTOT + off[lvl] + l];
    float c_ = (l + 0.5f) * (float)strides[lvl];
    float h  = lens[lvl][ap] * 0.5f;
    float s0 = rintf(c_ - h);
    float s1 = rintf(c_ + h);
    g_segs[((long long)b * ATOT + a) * 2 + 0] = __fadd_rn(s0, r0);
    g_segs[((long long)b * ATOT + a) * 2 + 1] = __fadd_rn(s1, r1);
}

// ---------------- per-batch bitonic sort (descending) ----------------
__global__ void sort_kernel()
{
    extern __shared__ unsigned long long s[];
    const int b = blockIdx.x;
    const int tid = threadIdx.x;

    for (int i = tid; i < NSORT; i += 1024) s[i] = g_keys[b * NSORT + i];
    __syncthreads();

    for (int k = 2; k <= NSORT; k <<= 1) {
        for (int j = k >> 1; j > 0; j >>= 1) {
            for (int i = tid; i < NSORT; i += 1024) {
                int ixj = i ^ j;
                if (ixj > i) {
                    unsigned long long va = s[i], vb = s[ixj];
                    bool desc = ((i & k) == 0);
                    if (desc ? (va < vb) : (va > vb)) { s[i] = vb; s[ixj] = va; }
                }
            }
            __syncthreads();
        }
    }
    for (int i = tid; i < KTOP; i += 1024) g_topkeys[b * KTOP + i] = s[i];
}

// ---------------- per-batch greedy NMS + output ----------------
__global__ void nms_kernel(float* __restrict__ out)
{
    __shared__ float s0[KTOP];
    __shared__ float s1[KTOP];
    __shared__ unsigned char sup[KTOP];

    const int b = blockIdx.x;
    const int tid = threadIdx.x;

    float myscore = 0.f, m0 = 0.f, m1 = 0.f;
    if (tid < KTOP) {
        unsigned long long key = g_topkeys[b * KTOP + tid];
        int a = (int)(0xFFFFFFFFu - (unsigned)(key & 0xFFFFFFFFull));
        unsigned mb = (unsigned)(key >> 32);
        mb ^= (mb & 0x80000000u) ? 0x80000000u : 0xFFFFFFFFu;
        float logit = __uint_as_float(mb);
        myscore = 1.f / (1.f + expf(-logit));
        m0 = g_segs[((long long)b * ATOT + a) * 2 + 0];
        m1 = g_segs[((long long)b * ATOT + a) * 2 + 1];
        s0[tid] = m0; s1[tid] = m1; sup[tid] = 0;
    }
    __syncthreads();

    const float mylen = __fadd_rn(m1, -m0);
    for (int i = 0; i < KTOP - 1; i++) {
        bool act = (sup[i] == 0);
        if (act && tid > i && tid < KTOP && sup[tid] == 0) {
            float a0 = s0[i], a1 = s1[i];
            float inter = fmaxf(__fadd_rn(fminf(a1, m1), -fmaxf(a0, m0)), 0.f);
            float uni = __fadd_rn(__fadd_rn(__fadd_rn(a1, -a0), mylen), -inter);
            float iou = __fdiv_rn(inter, fmaxf(uni, 1e-6f));
            if (iou > 0.5f) sup[tid] = 1;
        }
        __syncthreads();
    }

    if (tid < KTOP) {
        out[((long long)b * KTOP + tid) * 3 + 0] = sup[tid] ? 0.f : myscore;
        out[((long long)b * KTOP + tid) * 3 + 1] = m0;
        out[((long long)b * KTOP + tid) * 3 + 2] = m1;
    }
}

// ---------------- launch ----------------
extern "C" void kernel_launch(void* const* d_in, const int* in_sizes, int n_in,
                              void* d_out, int out_size)
{
    const float* feats[3] = {(const float*)d_in[0], (const float*)d_in[1], (const float*)d_in[2]};
    const float* cls_w  = (const float*)d_in[3];
    const float* cls_b  = (const float*)d_in[4];
    const float* reg_w  = (const float*)d_in[5];
    const float* reg_b  = (const float*)d_in[6];
    const float* clsp_w = (const float*)d_in[7];
    const float* clsp_b = (const float*)d_in[8];
    const float* regp_w = (const float*)d_in[9];
    const float* regp_b = (const float*)d_in[10];
    float* out = (float*)d_out;

    void* p;
    cudaGetSymbolAddress(&p, g_bufA); float* Ac = (float*)p;
    cudaGetSymbolAddress(&p, g_bufB); float* Bc = (float*)p;
    cudaGetSymbolAddress(&p, g_bufC); float* Ar = (float*)p;
    cudaGetSymbolAddress(&p, g_bufD); float* Br = (float*)p;
    cudaGetSymbolAddress(&p, g_logits); float* logits = (float*)p;
    cudaGetSymbolAddress(&p, g_regs);   float* regs = (float*)p;

    wtrans_kernel<<<6144, 256>>>(cls_w, reg_w);

    float* in_c = nullptr; float* in_r = nullptr;
    float* out_c = Ac;     float* out_r = Ar;

    for (int layer = 0; layer < 4; layer++) {
        gemm_kernel<<<dim3(224, 2, 6), 256>>>(feats[0], feats[1], feats[2],
                                              in_c, in_r, layer);
        combine_kernel<<<4096, 896>>>(out_c, out_r,
                                      cls_b + layer * 256, reg_b + layer * 256);
        in_c = out_c; in_r = out_r;
        out_c = (out_c == Ac) ? Bc : Ac;
        out_r = (out_r == Ar) ? Br : Ar;
    }

    convpred_kernel<<<dim3(56, BB, 2), 320>>>(in_c, in_r,
                                              clsp_w, regp_w, clsp_b, regp_b,
                                              logits, regs);

    score_kernel<<<(BB * NSORT) / 256, 256>>>();

    cudaFuncSetAttribute(sort_kernel, cudaFuncAttributeMaxDynamicSharedMemorySize,
                         NSORT * (int)sizeof(unsigned long long));
    sort_kernel<<<BB, 1024, NSORT * sizeof(unsigned long long)>>>();

    nms_kernel<<<BB, 1024>>>(out);
}

// round 16
// speedup vs baseline: 1.2390x; 1.2390x over previous
#include <cuda_runtime.h>
#include <math.h>

#define BB    8
#define CC    256
#define NCLS  20
#define APER  2
#define LTOT  3584
#define ATOT  7168
#define KTOP  1000
#define NSORT 8192

typedef unsigned long long u64;

// ---------------- scratch (device globals; no allocation) ----------------
__device__ float g_bufA[BB * CC * LTOT];   // cls ping
__device__ float g_bufB[BB * CC * LTOT];   // cls pong
__device__ float g_bufC[BB * CC * LTOT];   // reg ping
__device__ float g_bufD[BB * CC * LTOT];   // reg pong
__device__ float g_Gc[3 * BB * CC * LTOT]; // per-kw partials, cls tower
__device__ float g_Gr[3 * BB * CC * LTOT]; // per-kw partials, reg tower
__device__ float g_wt_c[4 * 3 * CC * CC];  // transposed weights [layer][kw][ci][co]
__device__ float g_wt_r[4 * 3 * CC * CC];
__device__ float g_logits[BB * APER * NCLS * LTOT];
__device__ float g_regs[BB * APER * 2 * LTOT];
__device__ float g_segs[BB * ATOT * 2];

// ---------------- packed f32x2 helpers ----------------
__device__ __forceinline__ u64 fma2(u64 a, u64 b, u64 c)
{
    u64 d;
    asm("fma.rn.f32x2 %0, %1, %2, %3;" : "=l"(d) : "l"(a), "l"(b), "l"(c));
    return d;
}
__device__ __forceinline__ u64 pk(float lo, float hi)
{
    u64 d;
    asm("mov.b64 %0, {%1, %2};" : "=l"(d) : "f"(lo), "f"(hi));
    return d;
}

// ---------------- weight transpose (ALL layers) --------------------------
__global__ void wtrans_kernel(const float* __restrict__ wc,
                              const float* __restrict__ wr)
{
    int idx = blockIdx.x * 256 + threadIdx.x;      // 0 .. 2*786432-1
    int tower = idx / 786432;
    int r = idx - tower * 786432;                  // [layer][kw][ci][co]
    int layer = r / 196608;
    int rr = r - layer * 196608;
    int kw = rr / 65536;
    int rem = rr - kw * 65536;
    int ci = rem >> 8;
    int co = rem & 255;
    const float* w = tower ? wr : wc;
    float v = w[layer * 196608 + co * 768 + ci * 3 + kw];
    (tower ? g_wt_r : g_wt_c)[r] = v;
}

// ---------------- per-kw GEMM: FFMA2 + cp.async.cg (R14 proven config) ---
// G_kw[co][l] = sum_ci wt[kw][ci][co] * x[ci][l]; single sequential fma
// chain per output lane over ci=0..255 (one Eigen k-block); bit-exact.
__global__ void __launch_bounds__(256, 2) gemm_kernel(
    const float* __restrict__ f3, const float* __restrict__ f4,
    const float* __restrict__ f5,
    const float* __restrict__ xc, const float* __restrict__ xr,
    int layer)
{
    __shared__ float xs[2][16][128];
    __shared__ float ws[2][16][128];

    const int tid = threadIdx.x;
    const int lbb = blockIdx.x;
    const int b = lbb / 28;
    const int lb = lbb - b * 28;
    const int lvl = (lb < 16) ? 0 : ((lb < 24) ? 1 : 2);
    const int Ls[3]  = {2048, 1024, 512};
    const int off[3] = {0, 2048, 3072};
    const int st[3]  = {0, 16, 24};
    const int lBase = (lb - st[lvl]) * 128;
    const int coBase = blockIdx.y * 128;
    const int z = blockIdx.z;
    const int tower = z / 3;
    const int kw = z - tower * 3;

    const float* x;
    int xcs_;
    long long xofs;
    if (layer == 0) {
        x = (lvl == 0) ? f3 : ((lvl == 1) ? f4 : f5);
        xcs_ = Ls[lvl];
        xofs = (long long)b * (256 * Ls[lvl]);
    } else {
        x = tower ? xr : xc;
        xcs_ = LTOT;
        xofs = (long long)b * (256 * LTOT) + off[lvl];
    }
    const float* wt = (tower ? g_wt_r : g_wt_c) + layer * 196608 + kw * 65536 + coBase;
    float* G = tower ? g_Gr : g_Gc;

    u64 acc2[8][4];
#pragma unroll
    for (int o = 0; o < 8; o++)
#pragma unroll
        for (int p = 0; p < 4; p++) acc2[o][p] = 0ULL;

    const int lg = tid & 15;
    const int cg = tid >> 4;
    const int lb8 = lg * 8;
    const int cb = cg * 8;

    const int ldrow = tid >> 4;        // 0..15 (ci within chunk)
    const int ldcol = (tid & 15) * 8;  // 0..120

    const float* xbase = x + xofs + (long long)ldrow * xcs_ + lBase + ldcol;
    const float* wbase = wt + ldrow * 256 + ldcol;

#define ISSUE(c0, stg) do {                                                   \
        const float* xp = xbase + (long long)(c0) * xcs_;                     \
        unsigned xd = (unsigned)__cvta_generic_to_shared(&xs[stg][ldrow][ldcol]); \
        asm volatile("cp.async.cg.shared.global [%0], [%1], 16;" ::  "r"(xd), "l"(xp) : "memory"); \
        asm volatile("cp.async.cg.shared.global [%0], [%1], 16;" ::  "r"(xd + 16), "l"(xp + 4) : "memory"); \
        const float* wp = wbase + (c0) * 256;                                 \
        unsigned wd = (unsigned)__cvta_generic_to_shared(&ws[stg][ldrow][ldcol]); \
        asm volatile("cp.async.cg.shared.global [%0], [%1], 16;" ::  "r"(wd), "l"(wp) : "memory"); \
        asm volatile("cp.async.cg.shared.global [%0], [%1], 16;" ::  "r"(wd + 16), "l"(wp + 4) : "memory"); \
        asm volatile("cp.async.commit_group;" ::: "memory");                  \
    } while (0)

    ISSUE(0, 0);

    for (int n = 0; n < 16; n++) {
        const int stg = n & 1;
        if (n < 15) {
            ISSUE(n * 16 + 16, stg ^ 1);
            asm volatile("cp.async.wait_group 1;" ::: "memory");
        } else {
            asm volatile("cp.async.wait_group 0;" ::: "memory");
        }
        __syncthreads();

#pragma unroll
        for (int ci = 0; ci < 16; ci++) {
            // adjacent-l float pairs in smem ARE packed f32x2 lanes
            ulonglong2 xa = *(const ulonglong2*)&xs[stg][ci][lb8];
            ulonglong2 xb = *(const ulonglong2*)&xs[stg][ci][lb8 + 4];
            float4 wa = *(const float4*)&ws[stg][ci][cb];
            float4 wb = *(const float4*)&ws[stg][ci][cb + 4];
            u64 xv[4] = {xa.x, xa.y, xb.x, xb.y};
            float wv[8] = {wa.x, wa.y, wa.z, wa.w, wb.x, wb.y, wb.z, wb.w};
#pragma unroll
            for (int o = 0; o < 8; o++) {
                u64 w2 = pk(wv[o], wv[o]);
#pragma unroll
                for (int p = 0; p < 4; p++)
                    acc2[o][p] = fma2(w2, xv[p], acc2[o][p]);
            }
        }
        __syncthreads();
    }
#undef ISSUE

#pragma unroll
    for (int o = 0; o < 8; o++) {
        u64* gp = (u64*)(G + ((long long)((kw * BB + b) * CC + coBase + cb + o)) * LTOT
                           + off[lvl] + lBase + lb8);
#pragma unroll
        for (int p = 0; p < 4; p++) gp[p] = acc2[o][p];
    }
}

// ---------------- combine: vectorized + smem halo staging (R14 proven) ---
__global__ void __launch_bounds__(128) combine_kernel(
    float* __restrict__ outc, float* __restrict__ outr,
    const float* __restrict__ bc, const float* __restrict__ br)
{
    __shared__ float s0[513];   // s0[i] = G0[l0 - 1 + i]
    __shared__ float s2[513];   // s2[i] = G2[l0 + i]

    const int tid = threadIdx.x;
    const int c = blockIdx.x;              // chunk 0..6 (512 l each)
    const int row = blockIdx.y;            // tower*2048 + b*256 + co
    const int co = row & 255;
    const int b = (row >> 8) & 7;
    const int tower = row >> 11;

    const int l0 = c * 512;
    const int lvlstart = (c < 4) ? 0 : ((c < 6) ? 2048 : 3072);
    const int lvlend   = (c < 4) ? 2048 : ((c < 6) ? 3072 : 3584);

    const float* G = tower ? g_Gr : g_Gc;
    long long base = ((long long)b * CC + co) * LTOT;
    const float* G0 = G + base;
    const float* G1 = G + (long long)BB * CC * LTOT + base;
    const float* G2 = G + 2LL * BB * CC * LTOT + base;
    float bias = (tower ? br : bc)[co];
    float* out = (tower ? outr : outc) + base;

    const int k = tid * 4;
    float4 a0 = *(const float4*)(G0 + l0 + k);
    float4 a2 = *(const float4*)(G2 + l0 + k);
    s0[1 + k]     = a0.x;
    s0[1 + k + 1] = a0.y;
    s0[1 + k + 2] = a0.z;
    s0[1 + k + 3] = a0.w;
    s2[k] = a2.x; s2[k + 1] = a2.y; s2[k + 2] = a2.z; s2[k + 3] = a2.w;
    if (tid == 0) {
        s0[0]   = (l0 > lvlstart) ? G0[l0 - 1] : 0.f;
        s2[512] = (l0 + 512 < lvlend) ? G2[l0 + 512] : 0.f;
    }
    __syncthreads();

    float4 g1 = *(const float4*)(G1 + l0 + k);
    float4 r;
    r.x = fmaxf(__fadd_rn(__fadd_rn(__fadd_rn(s0[k],     g1.x), s2[k + 1]), bias), 0.f);
    r.y = fmaxf(__fadd_rn(__fadd_rn(__fadd_rn(s0[k + 1], g1.y), s2[k + 2]), bias), 0.f);
    r.z = fmaxf(__fadd_rn(__fadd_rn(__fadd_rn(s0[k + 2], g1.z), s2[k + 3]), bias), 0.f);
    r.w = fmaxf(__fadd_rn(__fadd_rn(__fadd_rn(s0[k + 3], g1.w), s2[k + 4]), bias), 0.f);
    *(float4*)(out + l0 + k) = r;
}

// ---------------- fused prediction conv: x staged ONCE, 3 kw accums ------
__global__ void __launch_bounds__(320) convpred_kernel(
    const float* __restrict__ xc, const float* __restrict__ xr,
    const float* __restrict__ wcp, const float* __restrict__ wrp,
    const float* __restrict__ bcp, const float* __restrict__ brp,
    float* __restrict__ logits, float* __restrict__ regs)
{
    __shared__ float xs[32][72];
    __shared__ float ws[32][3][40];

    const int Ls[3]  = {2048, 1024, 512};
    const int off[3] = {0, 2048, 3072};
    const int st[3]  = {0, 32, 48};

    const int tid = threadIdx.x;
    const int pb = blockIdx.x;
    const int lvl = (pb < 32) ? 0 : ((pb < 48) ? 1 : 2);
    const int lBase = (pb - st[lvl]) * 64;
    const int b = blockIdx.y;
    const int tower = blockIdx.z;
    const int L = Ls[lvl];

    const int Cout = tower ? (APER * 2) : (APER * NCLS);
    const float* w = tower ? wrp : wcp;
    const float* bias = tower ? brp : bcp;
    const float* xb = (tower ? xr : xc) + (long long)b * (CC * LTOT) + off[lvl];
    float* y = (tower ? regs : logits) + (long long)b * (Cout * LTOT) + off[lvl];

    const int co = tid >> 3;
    const int lg = tid & 7;

    float p0[8], p1[8], p2[8];
#pragma unroll
    for (int q = 0; q < 8; q++) { p0[q] = 0.f; p1[q] = 0.f; p2[q] = 0.f; }

    const int wcount = Cout * 96;
    for (int c0 = 0; c0 < 256; c0 += 32) {
        for (int idx = tid; idx < 32 * 66; idx += 320) {
            int ci = idx / 66;
            int ll = idx - ci * 66;
            int gl = lBase + ll - 1;
            xs[ci][ll] = (gl >= 0 && gl < L) ? xb[(long long)(c0 + ci) * LTOT + gl] : 0.f;
        }
        for (int idx = tid; idx < wcount; idx += 320) {
            int c = idx / 96;
            int rem = idx - c * 96;
            int r = rem / 3;
            int kw = rem - r * 3;
            ws[r][kw][c] = w[c * 768 + (c0 + r) * 3 + kw];
        }
        __syncthreads();

        if (co < Cout) {
#pragma unroll
            for (int ci = 0; ci < 32; ci++) {
                float xv[10];
#pragma unroll
                for (int j = 0; j < 10; j++) xv[j] = xs[ci][lg * 8 + j];
                float w0 = ws[ci][0][co];
                float w1 = ws[ci][1][co];
                float w2 = ws[ci][2][co];
#pragma unroll
                for (int q = 0; q < 8; q++) {
                    p0[q] = fmaf(w0, xv[q],     p0[q]);
                    p1[q] = fmaf(w1, xv[q + 1], p1[q]);
                    p2[q] = fmaf(w2, xv[q + 2], p2[q]);
                }
            }
        }
        __syncthreads();
    }

    if (co < Cout) {
        float bv = bias[co];
#pragma unroll
        for (int q = 0; q < 8; q++)
            y[(long long)co * LTOT + lBase + lg * 8 + q] =
                __fadd_rn(__fadd_rn(__fadd_rn(p0[q], p1[q]), p2[q]), bv);
    }
}

// ---------------- fused tail: score + bitonic sort + NMS + output --------
// One block per batch. Dynamic smem: u64 keys[8192] | s0,s1[1000] | sup[1000].
__global__ void __launch_bounds__(1024) tail_kernel(float* __restrict__ out)
{
    extern __shared__ char smem_dyn[];
    u64* keys = (u64*)smem_dyn;                       // [8192]
    float* s0 = (float*)(smem_dyn + 65536);           // [1000]
    float* s1 = s0 + KTOP;                            // [1000]
    unsigned char* sup = (unsigned char*)(s1 + KTOP); // [1000]

    const int b = blockIdx.x;
    const int tid = threadIdx.x;

    const int   Ls[3]     = {2048, 1024, 512};
    const int   off[3]    = {0, 2048, 3072};
    const int   strides[3]= {8, 16, 32};
    const float lens[3][2]= {{16.f, 32.f}, {64.f, 128.f}, {256.f, 512.f}};

    // ---- score: build keys + segs ----
    for (int a = tid; a < NSORT; a += 1024) {
        if (a >= ATOT) { keys[a] = 0ULL; continue; }
        int lvl, al;
        if (a < 4096)      { lvl = 0; al = a; }
        else if (a < 6144) { lvl = 1; al = a - 4096; }
        else               { lvl = 2; al = a - 6144; }
        int L = Ls[lvl];
        int ap = al / L;
        int l  = al - ap * L;

        const float* lp = g_logits + ((long long)(b * APER + ap) * NCLS) * LTOT + off[lvl] + l;
        float m = -1e30f;
#pragma unroll
        for (int c = 0; c < NCLS; c++) m = fmaxf(m, lp[c * LTOT]);

        unsigned mb = __float_as_uint(m);
        mb ^= (mb & 0x80000000u) ? 0xFFFFFFFFu : 0x80000000u;
        keys[a] = ((unsigned long long)mb << 32) |
                  (unsigned long long)(0xFFFFFFFFu - (unsigned)a);

        float r0 = g_regs[((long long)(b * APER + ap) * 2 + 0) * LTOT + off[lvl] + l];
        float r1 = g_regs[((long long)(b * APER + ap) * 2 + 1) * LTOT + off[lvl] + l];
        float c_ = (l + 0.5f) * (float)strides[lvl];
        float h  = lens[lvl][ap] * 0.5f;
        g_segs[((long long)b * ATOT + a) * 2 + 0] = __fadd_rn(rintf(c_ - h), r0);
        g_segs[((long long)b * ATOT + a) * 2 + 1] = __fadd_rn(rintf(c_ + h), r1);
    }
    __syncthreads();

    // ---- bitonic sort descending ----
    for (int k = 2; k <= NSORT; k <<= 1) {
        for (int j = k >> 1; j > 0; j >>= 1) {
            for (int i = tid; i < NSORT; i += 1024) {
                int ixj = i ^ j;
                if (ixj > i) {
                    u64 va = keys[i], vb = keys[ixj];
                    bool desc = ((i & k) == 0);
                    if (desc ? (va < vb) : (va > vb)) { keys[i] = vb; keys[ixj] = va; }
                }
            }
            __syncthreads();
        }
    }

    // ---- NMS on top-1000 ----
    float myscore = 0.f, m0 = 0.f, m1 = 0.f;
    if (tid < KTOP) {
        u64 key = keys[tid];
        int a = (int)(0xFFFFFFFFu - (unsigned)(key & 0xFFFFFFFFull));
        unsigned mb = (unsigned)(key >> 32);
        mb ^= (mb & 0x80000000u) ? 0x80000000u : 0xFFFFFFFFu;
        float logit = __uint_as_float(mb);
        myscore = 1.f / (1.f + expf(-logit));
        m0 = g_segs[((long long)b * ATOT + a) * 2 + 0];
        m1 = g_segs[((long long)b * ATOT + a) * 2 + 1];
        s0[tid] = m0; s1[tid] = m1; sup[tid] = 0;
    }
    __syncthreads();

    const float mylen = __fadd_rn(m1, -m0);
    for (int i = 0; i < KTOP - 1; i++) {
        bool act = (sup[i] == 0);
        if (act && tid > i && tid < KTOP && sup[tid] == 0) {
            float a0 = s0[i], a1 = s1[i];
            float inter = fmaxf(__fadd_rn(fminf(a1, m1), -fmaxf(a0, m0)), 0.f);
            float uni = __fadd_rn(__fadd_rn(__fadd_rn(a1, -a0), mylen), -inter);
            float iou = __fdiv_rn(inter, fmaxf(uni, 1e-6f));
            if (iou > 0.5f) sup[tid] = 1;
        }
        __syncthreads();
    }

    if (tid < KTOP) {
        out[((long long)b * KTOP + tid) * 3 + 0] = sup[tid] ? 0.f : myscore;
        out[((long long)b * KTOP + tid) * 3 + 1] = m0;
        out[((long long)b * KTOP + tid) * 3 + 2] = m1;
    }
}

// ---------------- launch ----------------
extern "C" void kernel_launch(void* const* d_in, const int* in_sizes, int n_in,
                              void* d_out, int out_size)
{
    const float* feats[3] = {(const float*)d_in[0], (const float*)d_in[1], (const float*)d_in[2]};
    const float* cls_w  = (const float*)d_in[3];
    const float* cls_b  = (const float*)d_in[4];
    const float* reg_w  = (const float*)d_in[5];
    const float* reg_b  = (const float*)d_in[6];
    const float* clsp_w = (const float*)d_in[7];
    const float* clsp_b = (const float*)d_in[8];
    const float* regp_w = (const float*)d_in[9];
    const float* regp_b = (const float*)d_in[10];
    float* out = (float*)d_out;

    void* p;
    cudaGetSymbolAddress(&p, g_bufA); float* Ac = (float*)p;
    cudaGetSymbolAddress(&p, g_bufB); float* Bc = (float*)p;
    cudaGetSymbolAddress(&p, g_bufC); float* Ar = (float*)p;
    cudaGetSymbolAddress(&p, g_bufD); float* Br = (float*)p;
    cudaGetSymbolAddress(&p, g_logits); float* logits = (float*)p;
    cudaGetSymbolAddress(&p, g_regs);   float* regs = (float*)p;

    wtrans_kernel<<<6144, 256>>>(cls_w, reg_w);

    float* in_c = nullptr; float* in_r = nullptr;
    float* out_c = Ac;     float* out_r = Ar;

    for (int layer = 0; layer < 4; layer++) {
        gemm_kernel<<<dim3(224, 2, 6), 256>>>(feats[0], feats[1], feats[2],
                                              in_c, in_r, layer);
        combine_kernel<<<dim3(7, 4096), 128>>>(out_c, out_r,
                                               cls_b + layer * 256, reg_b + layer * 256);
        in_c = out_c; in_r = out_r;
        out_c = (out_c == Ac) ? Bc : Ac;
        out_r = (out_r == Ar) ? Br : Ar;
    }

    convpred_kernel<<<dim3(56, BB, 2), 320>>>(in_c, in_r,
                                              clsp_w, regp_w, clsp_b, regp_b,
                                              logits, regs);

    int tail_smem = NSORT * (int)sizeof(u64) + KTOP * 2 * (int)sizeof(float) + KTOP + 64;
    cudaFuncSetAttribute(tail_kernel, cudaFuncAttributeMaxDynamicSharedMemorySize,
                         tail_smem);
    tail_kernel<<<BB, 1024, tail_smem>>>(out);
}

// round 17
// speedup vs baseline: 1.2754x; 1.0293x over previous
#include <cuda_runtime.h>
#include <math.h>

#define BB    8
#define CC    256
#define NCLS  20
#define APER  2
#define LTOT  3584
#define ATOT  7168
#define KTOP  1000
#define NSORT 8192

typedef unsigned long long u64;

// ---------------- scratch (device globals; no allocation) ----------------
__device__ float g_bufA[BB * CC * LTOT];   // cls ping
__device__ float g_bufB[BB * CC * LTOT];   // cls pong
__device__ float g_bufC[BB * CC * LTOT];   // reg ping
__device__ float g_bufD[BB * CC * LTOT];   // reg pong
__device__ float g_Gc[3 * BB * CC * LTOT]; // per-kw partials, cls tower
__device__ float g_Gr[3 * BB * CC * LTOT]; // per-kw partials, reg tower
__device__ float g_wt_c[4 * 3 * CC * CC];  // transposed weights [layer][kw][ci][co]
__device__ float g_wt_r[4 * 3 * CC * CC];
__device__ float g_logits[BB * APER * NCLS * LTOT];
__device__ float g_regs[BB * APER * 2 * LTOT];
__device__ float g_segs[BB * ATOT * 2];

// ---------------- packed f32x2 helpers ----------------
__device__ __forceinline__ u64 fma2(u64 a, u64 b, u64 c)
{
    u64 d;
    asm("fma.rn.f32x2 %0, %1, %2, %3;" : "=l"(d) : "l"(a), "l"(b), "l"(c));
    return d;
}
__device__ __forceinline__ u64 pk(float lo, float hi)
{
    u64 d;
    asm("mov.b64 %0, {%1, %2};" : "=l"(d) : "f"(lo), "f"(hi));
    return d;
}

// ---------------- weight transpose (ALL layers) --------------------------
__global__ void wtrans_kernel(const float* __restrict__ wc,
                              const float* __restrict__ wr)
{
    int idx = blockIdx.x * 256 + threadIdx.x;      // 0 .. 2*786432-1
    int tower = idx / 786432;
    int r = idx - tower * 786432;                  // [layer][kw][ci][co]
    int layer = r / 196608;
    int rr = r - layer * 196608;
    int kw = rr / 65536;
    int rem = rr - kw * 65536;
    int ci = rem >> 8;
    int co = rem & 255;
    const float* w = tower ? wr : wc;
    float v = w[layer * 196608 + co * 768 + ci * 3 + kw];
    (tower ? g_wt_r : g_wt_c)[r] = v;
}

// ---------------- per-kw GEMM: FFMA2 + cp.async.cg (R16 proven config) ---
// G_kw[co][l] = sum_ci wt[kw][ci][co] * x[ci][l]; single sequential fma
// chain per output lane over ci=0..255 (one Eigen k-block); bit-exact.
// One tower per launch (tower param); blockIdx.z = kw.
__global__ void __launch_bounds__(256, 2) gemm_kernel(
    const float* __restrict__ f3, const float* __restrict__ f4,
    const float* __restrict__ f5,
    const float* __restrict__ xin,
    int layer, int tower)
{
    __shared__ float xs[2][16][128];
    __shared__ float ws[2][16][128];

    const int tid = threadIdx.x;
    const int lbb = blockIdx.x;
    const int b = lbb / 28;
    const int lb = lbb - b * 28;
    const int lvl = (lb < 16) ? 0 : ((lb < 24) ? 1 : 2);
    const int Ls[3]  = {2048, 1024, 512};
    const int off[3] = {0, 2048, 3072};
    const int st[3]  = {0, 16, 24};
    const int lBase = (lb - st[lvl]) * 128;
    const int coBase = blockIdx.y * 128;
    const int kw = blockIdx.z;

    const float* x;
    int xcs_;
    long long xofs;
    if (layer == 0) {
        x = (lvl == 0) ? f3 : ((lvl == 1) ? f4 : f5);
        xcs_ = Ls[lvl];
        xofs = (long long)b * (256 * Ls[lvl]);
    } else {
        x = xin;
        xcs_ = LTOT;
        xofs = (long long)b * (256 * LTOT) + off[lvl];
    }
    const float* wt = (tower ? g_wt_r : g_wt_c) + layer * 196608 + kw * 65536 + coBase;
    float* G = tower ? g_Gr : g_Gc;

    u64 acc2[8][4];
#pragma unroll
    for (int o = 0; o < 8; o++)
#pragma unroll
        for (int p = 0; p < 4; p++) acc2[o][p] = 0ULL;

    const int lg = tid & 15;
    const int cg = tid >> 4;
    const int lb8 = lg * 8;
    const int cb = cg * 8;

    const int ldrow = tid >> 4;        // 0..15 (ci within chunk)
    const int ldcol = (tid & 15) * 8;  // 0..120

    const float* xbase = x + xofs + (long long)ldrow * xcs_ + lBase + ldcol;
    const float* wbase = wt + ldrow * 256 + ldcol;

#define ISSUE(c0, stg) do {                                                   \
        const float* xp = xbase + (long long)(c0) * xcs_;                     \
        unsigned xd = (unsigned)__cvta_generic_to_shared(&xs[stg][ldrow][ldcol]); \
        asm volatile("cp.async.cg.shared.global [%0], [%1], 16;" ::  "r"(xd), "l"(xp) : "memory"); \
        asm volatile("cp.async.cg.shared.global [%0], [%1], 16;" ::  "r"(xd + 16), "l"(xp + 4) : "memory"); \
        const float* wp = wbase + (c0) * 256;                                 \
        unsigned wd = (unsigned)__cvta_generic_to_shared(&ws[stg][ldrow][ldcol]); \
        asm volatile("cp.async.cg.shared.global [%0], [%1], 16;" ::  "r"(wd), "l"(wp) : "memory"); \
        asm volatile("cp.async.cg.shared.global [%0], [%1], 16;" ::  "r"(wd + 16), "l"(wp + 4) : "memory"); \
        asm volatile("cp.async.commit_group;" ::: "memory");                  \
    } while (0)

    ISSUE(0, 0);

    for (int n = 0; n < 16; n++) {
        const int stg = n & 1;
        if (n < 15) {
            ISSUE(n * 16 + 16, stg ^ 1);
            asm volatile("cp.async.wait_group 1;" ::: "memory");
        } else {
            asm volatile("cp.async.wait_group 0;" ::: "memory");
        }
        __syncthreads();

#pragma unroll
        for (int ci = 0; ci < 16; ci++) {
            ulonglong2 xa = *(const ulonglong2*)&xs[stg][ci][lb8];
            ulonglong2 xb = *(const ulonglong2*)&xs[stg][ci][lb8 + 4];
            float4 wa = *(const float4*)&ws[stg][ci][cb];
            float4 wb = *(const float4*)&ws[stg][ci][cb + 4];
            u64 xv[4] = {xa.x, xa.y, xb.x, xb.y};
            float wv[8] = {wa.x, wa.y, wa.z, wa.w, wb.x, wb.y, wb.z, wb.w};
#pragma unroll
            for (int o = 0; o < 8; o++) {
                u64 w2 = pk(wv[o], wv[o]);
#pragma unroll
                for (int p = 0; p < 4; p++)
                    acc2[o][p] = fma2(w2, xv[p], acc2[o][p]);
            }
        }
        __syncthreads();
    }
#undef ISSUE

#pragma unroll
    for (int o = 0; o < 8; o++) {
        u64* gp = (u64*)(G + ((long long)((kw * BB + b) * CC + coBase + cb + o)) * LTOT
                           + off[lvl] + lBase + lb8);
#pragma unroll
        for (int p = 0; p < 4; p++) gp[p] = acc2[o][p];
    }
}

// ---------------- combine (single tower): smem halo staging --------------
__global__ void __launch_bounds__(128) combine_kernel(
    float* __restrict__ out_t, const float* __restrict__ bias_t, int tower)
{
    __shared__ float s0[513];   // s0[i] = G0[l0 - 1 + i]
    __shared__ float s2[513];   // s2[i] = G2[l0 + i]

    const int tid = threadIdx.x;
    const int c = blockIdx.x;              // chunk 0..6 (512 l each)
    const int row = blockIdx.y;            // b*256 + co
    const int co = row & 255;
    const int b = row >> 8;

    const int l0 = c * 512;
    const int lvlstart = (c < 4) ? 0 : ((c < 6) ? 2048 : 3072);
    const int lvlend   = (c < 4) ? 2048 : ((c < 6) ? 3072 : 3584);

    const float* G = tower ? g_Gr : g_Gc;
    long long base = ((long long)b * CC + co) * LTOT;
    const float* G0 = G + base;
    const float* G1 = G + (long long)BB * CC * LTOT + base;
    const float* G2 = G + 2LL * BB * CC * LTOT + base;
    float bias = bias_t[co];
    float* out = out_t + base;

    const int k = tid * 4;
    float4 a0 = *(const float4*)(G0 + l0 + k);
    float4 a2 = *(const float4*)(G2 + l0 + k);
    s0[1 + k]     = a0.x;
    s0[1 + k + 1] = a0.y;
    s0[1 + k + 2] = a0.z;
    s0[1 + k + 3] = a0.w;
    s2[k] = a2.x; s2[k + 1] = a2.y; s2[k + 2] = a2.z; s2[k + 3] = a2.w;
    if (tid == 0) {
        s0[0]   = (l0 > lvlstart) ? G0[l0 - 1] : 0.f;
        s2[512] = (l0 + 512 < lvlend) ? G2[l0 + 512] : 0.f;
    }
    __syncthreads();

    float4 g1 = *(const float4*)(G1 + l0 + k);
    float4 r;
    r.x = fmaxf(__fadd_rn(__fadd_rn(__fadd_rn(s0[k],     g1.x), s2[k + 1]), bias), 0.f);
    r.y = fmaxf(__fadd_rn(__fadd_rn(__fadd_rn(s0[k + 1], g1.y), s2[k + 2]), bias), 0.f);
    r.z = fmaxf(__fadd_rn(__fadd_rn(__fadd_rn(s0[k + 2], g1.z), s2[k + 3]), bias), 0.f);
    r.w = fmaxf(__fadd_rn(__fadd_rn(__fadd_rn(s0[k + 3], g1.w), s2[k + 4]), bias), 0.f);
    *(float4*)(out + l0 + k) = r;
}

// ---------------- prediction conv (single tower): x staged once ----------
__global__ void __launch_bounds__(320) convpred_kernel(
    const float* __restrict__ x_t,
    const float* __restrict__ w, const float* __restrict__ bias,
    float* __restrict__ y_t, int Cout)
{
    __shared__ float xs[32][72];
    __shared__ float ws[32][3][40];

    const int Ls[3]  = {2048, 1024, 512};
    const int off[3] = {0, 2048, 3072};
    const int st[3]  = {0, 32, 48};

    const int tid = threadIdx.x;
    const int pb = blockIdx.x;
    const int lvl = (pb < 32) ? 0 : ((pb < 48) ? 1 : 2);
    const int lBase = (pb - st[lvl]) * 64;
    const int b = blockIdx.y;
    const int L = Ls[lvl];

    const float* xb = x_t + (long long)b * (CC * LTOT) + off[lvl];
    float* y = y_t + (long long)b * (Cout * LTOT) + off[lvl];

    const int co = tid >> 3;
    const int lg = tid & 7;

    float p0[8], p1[8], p2[8];
#pragma unroll
    for (int q = 0; q < 8; q++) { p0[q] = 0.f; p1[q] = 0.f; p2[q] = 0.f; }

    const int wcount = Cout * 96;
    for (int c0 = 0; c0 < 256; c0 += 32) {
        for (int idx = tid; idx < 32 * 66; idx += 320) {
            int ci = idx / 66;
            int ll = idx - ci * 66;
            int gl = lBase + ll - 1;
            xs[ci][ll] = (gl >= 0 && gl < L) ? xb[(long long)(c0 + ci) * LTOT + gl] : 0.f;
        }
        for (int idx = tid; idx < wcount; idx += 320) {
            int c = idx / 96;
            int rem = idx - c * 96;
            int r = rem / 3;
            int kw = rem - r * 3;
            ws[r][kw][c] = w[c * 768 + (c0 + r) * 3 + kw];
        }
        __syncthreads();

        if (co < Cout) {
#pragma unroll
            for (int ci = 0; ci < 32; ci++) {
                float xv[10];
#pragma unroll
                for (int j = 0; j < 10; j++) xv[j] = xs[ci][lg * 8 + j];
                float w0 = ws[ci][0][co];
                float w1 = ws[ci][1][co];
                float w2 = ws[ci][2][co];
#pragma unroll
                for (int q = 0; q < 8; q++) {
                    p0[q] = fmaf(w0, xv[q],     p0[q]);
                    p1[q] = fmaf(w1, xv[q + 1], p1[q]);
                    p2[q] = fmaf(w2, xv[q + 2], p2[q]);
                }
            }
        }
        __syncthreads();
    }

    if (co < Cout) {
        float bv = bias[co];
#pragma unroll
        for (int q = 0; q < 8; q++)
            y[(long long)co * LTOT + lBase + lg * 8 + q] =
                __fadd_rn(__fadd_rn(__fadd_rn(p0[q], p1[q]), p2[q]), bv);
    }
}

// ---------------- fused tail: score + bitonic sort + NMS + output --------
__global__ void __launch_bounds__(1024) tail_kernel(float* __restrict__ out)
{
    extern __shared__ char smem_dyn[];
    u64* keys = (u64*)smem_dyn;                       // [8192]
    float* s0 = (float*)(smem_dyn + 65536);           // [1000]
    float* s1 = s0 + KTOP;                            // [1000]
    unsigned char* sup = (unsigned char*)(s1 + KTOP); // [1000]

    const int b = blockIdx.x;
    const int tid = threadIdx.x;

    const int   Ls[3]     = {2048, 1024, 512};
    const int   off[3]    = {0, 2048, 3072};
    const int   strides[3]= {8, 16, 32};
    const float lens[3][2]= {{16.f, 32.f}, {64.f, 128.f}, {256.f, 512.f}};

    for (int a = tid; a < NSORT; a += 1024) {
        if (a >= ATOT) { keys[a] = 0ULL; continue; }
        int lvl, al;
        if (a < 4096)      { lvl = 0; al = a; }
        else if (a < 6144) { lvl = 1; al = a - 4096; }
        else               { lvl = 2; al = a - 6144; }
        int L = Ls[lvl];
        int ap = al / L;
        int l  = al - ap * L;

        const float* lp = g_logits + ((long long)(b * APER + ap) * NCLS) * LTOT + off[lvl] + l;
        float m = -1e30f;
#pragma unroll
        for (int c = 0; c < NCLS; c++) m = fmaxf(m, lp[c * LTOT]);

        unsigned mb = __float_as_uint(m);
        mb ^= (mb & 0x80000000u) ? 0xFFFFFFFFu : 0x80000000u;
        keys[a] = ((unsigned long long)mb << 32) |
                  (unsigned long long)(0xFFFFFFFFu - (unsigned)a);

        float r0 = g_regs[((long long)(b * APER + ap) * 2 + 0) * LTOT + off[lvl] + l];
        float r1 = g_regs[((long long)(b * APER + ap) * 2 + 1) * LTOT + off[lvl] + l];
        float c_ = (l + 0.5f) * (float)strides[lvl];
        float h  = lens[lvl][ap] * 0.5f;
        g_segs[((long long)b * ATOT + a) * 2 + 0] = __fadd_rn(rintf(c_ - h), r0);
        g_segs[((long long)b * ATOT + a) * 2 + 1] = __fadd_rn(rintf(c_ + h), r1);
    }
    __syncthreads();

    for (int k = 2; k <= NSORT; k <<= 1) {
        for (int j = k >> 1; j > 0; j >>= 1) {
            for (int i = tid; i < NSORT; i += 1024) {
                int ixj = i ^ j;
                if (ixj > i) {
                    u64 va = keys[i], vb = keys[ixj];
                    bool desc = ((i & k) == 0);
                    if (desc ? (va < vb) : (va > vb)) { keys[i] = vb; keys[ixj] = va; }
                }
            }
            __syncthreads();
        }
    }

    float myscore = 0.f, m0 = 0.f, m1 = 0.f;
    if (tid < KTOP) {
        u64 key = keys[tid];
        int a = (int)(0xFFFFFFFFu - (unsigned)(key & 0xFFFFFFFFull));
        unsigned mb = (unsigned)(key >> 32);
        mb ^= (mb & 0x80000000u) ? 0x80000000u : 0xFFFFFFFFu;
        float logit = __uint_as_float(mb);
        myscore = 1.f / (1.f + expf(-logit));
        m0 = g_segs[((long long)b * ATOT + a) * 2 + 0];
        m1 = g_segs[((long long)b * ATOT + a) * 2 + 1];
        s0[tid] = m0; s1[tid] = m1; sup[tid] = 0;
    }
    __syncthreads();

    const float mylen = __fadd_rn(m1, -m0);
    for (int i = 0; i < KTOP - 1; i++) {
        bool act = (sup[i] == 0);
        if (act && tid > i && tid < KTOP && sup[tid] == 0) {
            float a0 = s0[i], a1 = s1[i];
            float inter = fmaxf(__fadd_rn(fminf(a1, m1), -fmaxf(a0, m0)), 0.f);
            float uni = __fadd_rn(__fadd_rn(__fadd_rn(a1, -a0), mylen), -inter);
            float iou = __fdiv_rn(inter, fmaxf(uni, 1e-6f));
            if (iou > 0.5f) sup[tid] = 1;
        }
        __syncthreads();
    }

    if (tid < KTOP) {
        out[((long long)b * KTOP + tid) * 3 + 0] = sup[tid] ? 0.f : myscore;
        out[((long long)b * KTOP + tid) * 3 + 1] = m0;
        out[((long long)b * KTOP + tid) * 3 + 2] = m1;
    }
}

// ---------------- launch: two-stream tower parallelism -------------------
extern "C" void kernel_launch(void* const* d_in, const int* in_sizes, int n_in,
                              void* d_out, int out_size)
{
    const float* feats[3] = {(const float*)d_in[0], (const float*)d_in[1], (const float*)d_in[2]};
    const float* cls_w  = (const float*)d_in[3];
    const float* cls_b  = (const float*)d_in[4];
    const float* reg_w  = (const float*)d_in[5];
    const float* reg_b  = (const float*)d_in[6];
    const float* clsp_w = (const float*)d_in[7];
    const float* clsp_b = (const float*)d_in[8];
    const float* regp_w = (const float*)d_in[9];
    const float* regp_b = (const float*)d_in[10];
    float* out = (float*)d_out;

    void* p;
    cudaGetSymbolAddress(&p, g_bufA); float* Ac = (float*)p;
    cudaGetSymbolAddress(&p, g_bufB); float* Bc = (float*)p;
    cudaGetSymbolAddress(&p, g_bufC); float* Ar = (float*)p;
    cudaGetSymbolAddress(&p, g_bufD); float* Br = (float*)p;
    cudaGetSymbolAddress(&p, g_logits); float* logits = (float*)p;
    cudaGetSymbolAddress(&p, g_regs);   float* regs = (float*)p;

    // streams/events created once, on the (uncaptured) correctness call
    static cudaStream_t st0 = nullptr, st1 = nullptr;
    static cudaEvent_t ev_fork = nullptr, ev_j0 = nullptr, ev_j1 = nullptr;
    if (st0 == nullptr) {
        cudaStreamCreateWithFlags(&st0, cudaStreamNonBlocking);
        cudaStreamCreateWithFlags(&st1, cudaStreamNonBlocking);
        cudaEventCreateWithFlags(&ev_fork, cudaEventDisableTiming);
        cudaEventCreateWithFlags(&ev_j0, cudaEventDisableTiming);
        cudaEventCreateWithFlags(&ev_j1, cudaEventDisableTiming);
    }

    wtrans_kernel<<<6144, 256>>>(cls_w, reg_w);

    cudaEventRecord(ev_fork, 0);
    cudaStreamWaitEvent(st0, ev_fork, 0);
    cudaStreamWaitEvent(st1, ev_fork, 0);

    const float* tw_b[2]   = {cls_b, reg_b};
    const float* pw[2]     = {clsp_w, regp_w};
    const float* pb[2]     = {clsp_b, regp_b};
    float* ping[2] = {Ac, Ar};
    float* pong[2] = {Bc, Br};
    float* yout[2] = {logits, regs};
    const int couts[2] = {APER * NCLS, APER * 2};
    cudaStream_t strm[2] = {st0, st1};

    for (int t = 0; t < 2; t++) {
        float* in_t = nullptr;
        float* out_t = ping[t];
        for (int layer = 0; layer < 4; layer++) {
            gemm_kernel<<<dim3(224, 2, 3), 256, 0, strm[t]>>>(
                feats[0], feats[1], feats[2], in_t, layer, t);
            combine_kernel<<<dim3(7, 2048), 128, 0, strm[t]>>>(
                out_t, tw_b[t] + layer * 256, t);
            in_t = out_t;
            out_t = (out_t == ping[t]) ? pong[t] : ping[t];
        }
        convpred_kernel<<<dim3(56, BB), 320, 0, strm[t]>>>(
            in_t, pw[t], pb[t], yout[t], couts[t]);
    }

    cudaEventRecord(ev_j0, st0);
    cudaEventRecord(ev_j1, st1);
    cudaStreamWaitEvent(0, ev_j0, 0);
    cudaStreamWaitEvent(0, ev_j1, 0);

    int tail_smem = NSORT * (int)sizeof(u64) + KTOP * 2 * (int)sizeof(float) + KTOP + 64;
    cudaFuncSetAttribute(tail_kernel, cudaFuncAttributeMaxDynamicSharedMemorySize,
                         tail_smem);
    tail_kernel<<<BB, 1024, tail_smem>>>(out);
}